// round 4
// baseline (speedup 1.0000x reference)
#include <cuda_runtime.h>
#include <cuda_bf16.h>

#define NTOK 4096
#define HEADS 8
#define DH 128
#define NKEY 256
#define TOPK 32

static __device__ __forceinline__ float neg_inf() { return __int_as_float(0xff800000); }

// ---------------- scratch (no allocations allowed) ----------------
__device__ float g_q [(size_t)NTOK * 2048];              // 33.5 MB
__device__ float g_s1[(size_t)NTOK * HEADS * 2 * TOPK];  // stage-1 scores (sorted desc)
__device__ int   g_i1[(size_t)NTOK * HEADS * 2 * TOPK];  // stage-1 indices
__device__ float g_oh[(size_t)NTOK * 1024];              // per-head outputs (b,t, h*128+d)

// =================================================================
// SGEMM: C[M,N] = A[M,K] * B[N,K]^T (+ bias[N]).  fp32, 128x64x16.
// =================================================================
__global__ __launch_bounds__(256)
void sgemm_tn(const float* __restrict__ A, const float* __restrict__ B,
              float* __restrict__ C, const float* __restrict__ bias,
              int M, int N, int K, int lda, int ldb, int ldc)
{
    __shared__ float As[16][132];   // [k][m]
    __shared__ float Bs[16][68];    // [k][n]

    const int tid = threadIdx.x;
    const int m0 = blockIdx.y * 128;
    const int n0 = blockIdx.x * 64;
    const int ty = tid >> 4;        // 0..15 -> rows ty*8..+7
    const int tx = tid & 15;        // 0..15 -> cols tx*4..+3

    const int aRow0 = tid >> 2;             // 0..63
    const int aRow1 = aRow0 + 64;
    const int aK    = (tid & 3) << 2;
    const int bRow  = tid >> 2;
    const int bK    = (tid & 3) << 2;

    const float* Ap0 = A + (size_t)(m0 + aRow0) * lda + aK;
    const float* Ap1 = A + (size_t)(m0 + aRow1) * lda + aK;
    const float* Bp  = B + (size_t)(n0 + bRow) * ldb + bK;

    float4 ra0 = *(const float4*)Ap0;
    float4 ra1 = *(const float4*)Ap1;
    float4 rb  = *(const float4*)Bp;

    float acc[8][4];
    #pragma unroll
    for (int r = 0; r < 8; r++)
        #pragma unroll
        for (int c = 0; c < 4; c++) acc[r][c] = 0.f;

    const int nsteps = K >> 4;
    for (int s = 0; s < nsteps; s++) {
        __syncthreads();
        As[aK+0][aRow0] = ra0.x; As[aK+1][aRow0] = ra0.y;
        As[aK+2][aRow0] = ra0.z; As[aK+3][aRow0] = ra0.w;
        As[aK+0][aRow1] = ra1.x; As[aK+1][aRow1] = ra1.y;
        As[aK+2][aRow1] = ra1.z; As[aK+3][aRow1] = ra1.w;
        Bs[bK+0][bRow]  = rb.x;  Bs[bK+1][bRow]  = rb.y;
        Bs[bK+2][bRow]  = rb.z;  Bs[bK+3][bRow]  = rb.w;
        __syncthreads();
        if (s + 1 < nsteps) {
            ra0 = *(const float4*)(Ap0 + (s+1)*16);
            ra1 = *(const float4*)(Ap1 + (s+1)*16);
            rb  = *(const float4*)(Bp  + (s+1)*16);
        }
        #pragma unroll
        for (int kk = 0; kk < 16; kk++) {
            float4 av0 = *(const float4*)&As[kk][ty*8];
            float4 av1 = *(const float4*)&As[kk][ty*8+4];
            float4 bv  = *(const float4*)&Bs[kk][tx*4];
            float a8[8] = {av0.x, av0.y, av0.z, av0.w, av1.x, av1.y, av1.z, av1.w};
            float b4[4] = {bv.x, bv.y, bv.z, bv.w};
            #pragma unroll
            for (int r = 0; r < 8; r++)
                #pragma unroll
                for (int c = 0; c < 4; c++)
                    acc[r][c] = fmaf(a8[r], b4[c], acc[r][c]);
        }
    }

    float4 bv4 = make_float4(0.f, 0.f, 0.f, 0.f);
    if (bias) bv4 = *(const float4*)(bias + n0 + tx*4);
    #pragma unroll
    for (int r = 0; r < 8; r++) {
        float4 o;
        o.x = acc[r][0] + bv4.x;
        o.y = acc[r][1] + bv4.y;
        o.z = acc[r][2] + bv4.z;
        o.w = acc[r][3] + bv4.w;
        *(float4*)&C[(size_t)(m0 + ty*8 + r) * ldc + n0 + tx*4] = o;
    }
}

// =================================================================
// Kernel 2: for one (h,p) and a 32-token tile, compute dots vs all
// 256 keys, then per-token top-32 (desc, ties -> smaller index).
// q[p,b,t,h,d] = g_q[token*2048 + p*1024 + h*128 + d]
// keys[h,n,p,d] at h*65536 + n*256 + p*128 + d
// =================================================================
__global__ __launch_bounds__(256)
void dots_topk_kernel(const float* __restrict__ qm, const float* __restrict__ keys)
{
    __shared__ float As[8][36];     // [k][t]
    __shared__ float Bs[8][264];    // [k][n]
    __shared__ float dsm[32*256];   // [t][n]

    const int tid  = threadIdx.x;
    const int hp   = blockIdx.y;        // 0..15
    const int h    = hp >> 1;
    const int p    = hp & 1;
    const int t0g  = blockIdx.x * 32;   // global token tile (b*2048 + t)

    const int ty   = tid >> 5;          // warp 0..7 -> rows ty*4..+3
    const int lane = tid & 31;          // cols {lane*4..+3, 128+lane*4..+3}

    // A loader: 32 tokens x 8 k  (tid < 64)
    const int at = tid >> 1;            // 0..31
    const int ak = (tid & 1) << 2;
    const float* Ap = qm + (size_t)(t0g + at) * 2048 + p*1024 + h*DH + ak;

    // B loader: 256 keys x 8 k (2 float4 / thread)
    const int bn0 = tid >> 1;           // 0..127
    const int bn1 = bn0 + 128;
    const int bk  = (tid & 1) << 2;
    const float* Kb  = keys + (size_t)h * (NKEY*2*DH) + (size_t)p * DH;
    const float* Bp0 = Kb + (size_t)bn0 * (2*DH) + bk;
    const float* Bp1 = Kb + (size_t)bn1 * (2*DH) + bk;

    float4 ra = make_float4(0.f,0.f,0.f,0.f);
    if (tid < 64) ra = *(const float4*)Ap;
    float4 rb0 = *(const float4*)Bp0;
    float4 rb1 = *(const float4*)Bp1;

    float acc[4][8];
    #pragma unroll
    for (int r = 0; r < 4; r++)
        #pragma unroll
        for (int c = 0; c < 8; c++) acc[r][c] = 0.f;

    for (int s = 0; s < 16; s++) {      // K = 128, BK = 8
        __syncthreads();
        if (tid < 64) {
            As[ak+0][at] = ra.x; As[ak+1][at] = ra.y;
            As[ak+2][at] = ra.z; As[ak+3][at] = ra.w;
        }
        Bs[bk+0][bn0] = rb0.x; Bs[bk+1][bn0] = rb0.y;
        Bs[bk+2][bn0] = rb0.z; Bs[bk+3][bn0] = rb0.w;
        Bs[bk+0][bn1] = rb1.x; Bs[bk+1][bn1] = rb1.y;
        Bs[bk+2][bn1] = rb1.z; Bs[bk+3][bn1] = rb1.w;
        __syncthreads();
        if (s + 1 < 16) {
            if (tid < 64) ra = *(const float4*)(Ap + (s+1)*8);
            rb0 = *(const float4*)(Bp0 + (s+1)*8);
            rb1 = *(const float4*)(Bp1 + (s+1)*8);
        }
        #pragma unroll
        for (int kk = 0; kk < 8; kk++) {
            float4 a4 = *(const float4*)&As[kk][ty*4];
            float4 b0 = *(const float4*)&Bs[kk][lane*4];
            float4 b1 = *(const float4*)&Bs[kk][128 + lane*4];
            float ar[4] = {a4.x,a4.y,a4.z,a4.w};
            float bc[8] = {b0.x,b0.y,b0.z,b0.w,b1.x,b1.y,b1.z,b1.w};
            #pragma unroll
            for (int r = 0; r < 4; r++)
                #pragma unroll
                for (int c = 0; c < 8; c++)
                    acc[r][c] = fmaf(ar[r], bc[c], acc[r][c]);
        }
    }

    // spill dots to smem: dsm[t][n]
    #pragma unroll
    for (int r = 0; r < 4; r++) {
        *(float4*)&dsm[(ty*4+r)*256 + lane*4]       = make_float4(acc[r][0],acc[r][1],acc[r][2],acc[r][3]);
        *(float4*)&dsm[(ty*4+r)*256 + 128 + lane*4] = make_float4(acc[r][4],acc[r][5],acc[r][6],acc[r][7]);
    }
    __syncthreads();

    // warp ty: top-32 of 256 for tokens ty*4 + it.  lane owns n = j*32+lane.
    #pragma unroll 1
    for (int it = 0; it < 4; it++) {
        const int t = ty*4 + it;
        float v[8];
        #pragma unroll
        for (int j = 0; j < 8; j++) v[j] = dsm[t*256 + j*32 + lane];
        unsigned taken = 0u;
        float outv = 0.f; int outn = 0;
        #pragma unroll 1
        for (int kk = 0; kk < 32; kk++) {
            float lv = neg_inf(); int ln = 0x7fffffff;
            #pragma unroll
            for (int j = 0; j < 8; j++) {
                float cand = ((taken >> j) & 1u) ? neg_inf() : v[j];
                if (cand > lv) { lv = cand; ln = j*32 + lane; }
            }
            #pragma unroll
            for (int o = 16; o > 0; o >>= 1) {
                float ov = __shfl_xor_sync(0xffffffffu, lv, o);
                int   on = __shfl_xor_sync(0xffffffffu, ln, o);
                if (ov > lv || (ov == lv && on < ln)) { lv = ov; ln = on; }
            }
            if (kk == lane) { outv = lv; outn = ln; }        // sorted: slot kk
            if ((ln & 31) == lane) taken |= 1u << (ln >> 5); // consume winner
        }
        const size_t base = ((((size_t)(t0g + t)) * HEADS + h) * 2 + p) * TOPK;
        g_s1[base + lane] = outv;
        g_i1[base + lane] = outn;
    }
}

// =================================================================
// Kernel 3: per (b,h,t'): t' = 2u+p pairs token (b,u) with (b,u+1024).
// top-32 of s0[i]+s1[j] via sorted-column pointer merge, softmax,
// gather 32 value rows, weighted sum.
// =================================================================
__global__ __launch_bounds__(256)
void combine_kernel(const float* __restrict__ values)
{
    const int warp = threadIdx.x >> 5;
    const int lane = threadIdx.x & 31;
    const int slot = blockIdx.x * 8 + warp;   // 0..32767
    const int t = slot & 2047;
    const int h = (slot >> 11) & 7;
    const int b = slot >> 14;
    const int u = t >> 1;
    const int p = t & 1;

    const size_t base0 = ((((size_t)(b*2048 + u))        * HEADS + h) * 2 + p) * TOPK;
    const size_t base1 = ((((size_t)(b*2048 + u + 1024)) * HEADS + h) * 2 + p) * TOPK;
    const float s0 = g_s1[base0 + lane];   // sorted desc across lanes
    const int   i0 = g_i1[base0 + lane];
    const float s1 = g_s1[base1 + lane];
    const int   i1 = g_i1[base1 + lane];

    // lane = column j; candidates s0[ptr]+s1[j] descend as ptr advances.
    int ptr = 0;
    float rv = 0.f; int rflat = 0;
    #pragma unroll 1
    for (int it = 0; it < 32; it++) {
        const int pp = ptr < 32 ? ptr : 31;
        float cv = __shfl_sync(0xffffffffu, s0, pp) + s1;
        int fl = ptr * 32 + lane;                       // flat = i*32+j (jax order)
        if (ptr >= 32) { cv = neg_inf(); fl = 0x7fffffff; }
        float lv = cv; int ln = fl;
        #pragma unroll
        for (int o = 16; o > 0; o >>= 1) {
            float ov = __shfl_xor_sync(0xffffffffu, lv, o);
            int   on = __shfl_xor_sync(0xffffffffu, ln, o);
            if (ov > lv || (ov == lv && on < ln)) { lv = ov; ln = on; }
        }
        if (it == lane) { rv = lv; rflat = ln; }        // lane k = k-th largest
        if ((ln & 31) == lane && ln != 0x7fffffff) ptr++; // winning column advances
    }

    // softmax (lane 0 holds the max by construction)
    const float mx = __shfl_sync(0xffffffffu, rv, 0);
    float e = __expf(rv - mx);
    float ssum = e;
    #pragma unroll
    for (int o = 16; o > 0; o >>= 1) ssum += __shfl_xor_sync(0xffffffffu, ssum, o);
    const float w = e / ssum;

    const int si = rflat >> 5;
    const int sj = rflat & 31;
    const int iv0 = __shfl_sync(0xffffffffu, i0, si);
    const int iv1 = __shfl_sync(0xffffffffu, i1, sj);
    const int vi = iv0 * NKEY + iv1;

    // gather 32 value rows (512B each, coalesced across warp) + weighted sum
    const float* vb = values + (size_t)h * ((size_t)NKEY*NKEY) * DH;
    float4 acc = make_float4(0.f,0.f,0.f,0.f);
    #pragma unroll 1
    for (int k = 0; k < 32; k++) {
        const int   vik = __shfl_sync(0xffffffffu, vi, k);
        const float wk  = __shfl_sync(0xffffffffu, w,  k);
        const float4 row = *(const float4*)(vb + (size_t)vik * DH + lane*4);
        acc.x = fmaf(wk, row.x, acc.x);
        acc.y = fmaf(wk, row.y, acc.y);
        acc.z = fmaf(wk, row.z, acc.z);
        acc.w = fmaf(wk, row.w, acc.w);
    }
    *(float4*)&g_oh[(size_t)(b*2048 + t) * 1024 + h*DH + lane*4] = acc;
}

// =================================================================
extern "C" void kernel_launch(void* const* d_in, const int* in_sizes, int n_in,
                              void* d_out, int out_size)
{
    const float* x      = (const float*)d_in[0];
    const float* Wq     = (const float*)d_in[1];
    const float* keys   = (const float*)d_in[2];
    const float* values = (const float*)d_in[3];
    const float* Wo     = (const float*)d_in[4];
    const float* bo     = (const float*)d_in[5];
    float* out = (float*)d_out;

    float* q;  cudaGetSymbolAddress((void**)&q,  g_q);
    float* oh; cudaGetSymbolAddress((void**)&oh, g_oh);

    // 1) q = x @ Wq^T : [4096,1024] x [2048,1024]^T -> [4096,2048]
    sgemm_tn<<<dim3(2048/64, 4096/128), 256>>>(x, Wq, q, nullptr,
                                               4096, 2048, 1024, 1024, 1024, 2048);
    // 2) dots + stage-1 top-32
    dots_topk_kernel<<<dim3(4096/32, 16), 256>>>(q, keys);
    // 3) combine + softmax + gather
    combine_kernel<<<4096, 256>>>(values);
    // 4) out = oh @ Wo^T + bo : [4096,1024] x [1024,1024]^T -> [4096,1024]
    sgemm_tn<<<dim3(1024/64, 4096/128), 256>>>(oh, Wo, out, bo,
                                               4096, 1024, 1024, 1024, 1024, 1024);
}

// round 8
// speedup vs baseline: 1.3113x; 1.3113x over previous
#include <cuda_runtime.h>
#include <cuda_bf16.h>

#define NTOK 4096
#define HEADS 8
#define DH 128
#define NKEY 256
#define TOPK 32

static __device__ __forceinline__ float neg_inf() { return __int_as_float(0xff800000); }

// order-preserving float<->uint (total order, matches > on floats, no NaNs here)
static __device__ __forceinline__ unsigned ford(float f) {
    unsigned b = __float_as_uint(f);
    return (b & 0x80000000u) ? ~b : (b | 0x80000000u);
}
static __device__ __forceinline__ float forddec(unsigned u) {
    unsigned b = (u & 0x80000000u) ? (u & 0x7fffffffu) : ~u;
    return __uint_as_float(b);
}

// ---------------- scratch (no allocations allowed) ----------------
__device__ float g_q [(size_t)NTOK * 2048];              // 33.5 MB
__device__ float g_s1[(size_t)NTOK * HEADS * 2 * TOPK];  // stage-1 scores (sorted desc)
__device__ int   g_i1[(size_t)NTOK * HEADS * 2 * TOPK];  // stage-1 indices
__device__ float g_oh[(size_t)NTOK * 1024];              // per-head outputs

// =================================================================
// tf32x2 tensor-core GEMM: C[M,N] = A[M,K] * B[N,K]^T (+ bias[N]).
// Split-float (hi/lo) => ~fp32 accuracy, selection-safe.
// Block 128x128x16, 8 warps, warp tile 32x64, m16n8k8 HMMA.
// =================================================================
static __device__ __forceinline__ void mma1688(float* d, const unsigned* a, const unsigned* b) {
    asm volatile(
        "mma.sync.aligned.m16n8k8.row.col.f32.tf32.tf32.f32 "
        "{%0,%1,%2,%3}, {%4,%5,%6,%7}, {%8,%9}, {%0,%1,%2,%3};"
        : "+f"(d[0]), "+f"(d[1]), "+f"(d[2]), "+f"(d[3])
        : "r"(a[0]), "r"(a[1]), "r"(a[2]), "r"(a[3]), "r"(b[0]), "r"(b[1]));
}
static __device__ __forceinline__ void split_tf32(float f, unsigned& hi, unsigned& lo) {
    hi = __float_as_uint(f) & 0xffffe000u;                 // exactly tf32-representable
    lo = __float_as_uint(f - __uint_as_float(hi));         // residual (hw-truncated, fine)
}

__global__ __launch_bounds__(256)
void mma_tn_x2(const float* __restrict__ A, const float* __restrict__ B,
               float* __restrict__ C, const float* __restrict__ bias,
               int M, int N, int K, int lda, int ldb, int ldc)
{
    __shared__ float As[128][20];   // [m][k], stride 20 -> conflict-free frag loads
    __shared__ float Bs[128][20];   // [n][k]

    const int tid  = threadIdx.x;
    const int lane = tid & 31;
    const int wid  = tid >> 5;
    const int wm   = wid & 3;       // 4 warps along M
    const int wn   = wid >> 2;      // 2 warps along N
    const int m0   = blockIdx.y * 128;
    const int n0   = blockIdx.x * 128;

    // loaders: 512 float4 per tile; thread t handles f4 idx {t, t+256}
    const int r0 = tid >> 2;              // 0..63
    const int r1 = r0 + 64;               // 64..127
    const int kc = (tid & 3) << 2;        // 0,4,8,12

    const float* Ap0 = A + (size_t)(m0 + r0) * lda + kc;
    const float* Ap1 = A + (size_t)(m0 + r1) * lda + kc;
    const float* Bp0 = B + (size_t)(n0 + r0) * ldb + kc;
    const float* Bp1 = B + (size_t)(n0 + r1) * ldb + kc;

    float4 ra0 = *(const float4*)Ap0;
    float4 ra1 = *(const float4*)Ap1;
    float4 rb0 = *(const float4*)Bp0;
    float4 rb1 = *(const float4*)Bp1;

    float d[2][8][4];
    #pragma unroll
    for (int mt = 0; mt < 2; mt++)
        #pragma unroll
        for (int nt = 0; nt < 8; nt++)
            #pragma unroll
            for (int i = 0; i < 4; i++) d[mt][nt][i] = 0.f;

    const int frow = lane >> 2;     // fragment row/col offsets
    const int fcol = lane & 3;
    const int nsteps = K >> 4;

    for (int s = 0; s < nsteps; s++) {
        __syncthreads();
        *(float4*)&As[r0][kc] = ra0;
        *(float4*)&As[r1][kc] = ra1;
        *(float4*)&Bs[r0][kc] = rb0;
        *(float4*)&Bs[r1][kc] = rb1;
        __syncthreads();
        if (s + 1 < nsteps) {
            ra0 = *(const float4*)(Ap0 + (s+1)*16);
            ra1 = *(const float4*)(Ap1 + (s+1)*16);
            rb0 = *(const float4*)(Bp0 + (s+1)*16);
            rb1 = *(const float4*)(Bp1 + (s+1)*16);
        }
        #pragma unroll
        for (int k0 = 0; k0 < 16; k0 += 8) {
            // B fragments (hi/lo) for all 8 n-tiles
            unsigned bh[8][2], bl[8][2];
            #pragma unroll
            for (int nt = 0; nt < 8; nt++) {
                const int n = wn*64 + nt*8 + frow;
                float b0 = Bs[n][k0 + fcol];
                float b1 = Bs[n][k0 + fcol + 4];
                split_tf32(b0, bh[nt][0], bl[nt][0]);
                split_tf32(b1, bh[nt][1], bl[nt][1]);
            }
            #pragma unroll
            for (int mt = 0; mt < 2; mt++) {
                const int mb = wm*32 + mt*16;
                float a0 = As[mb + frow    ][k0 + fcol    ];
                float a1 = As[mb + frow + 8][k0 + fcol    ];
                float a2 = As[mb + frow    ][k0 + fcol + 4];
                float a3 = As[mb + frow + 8][k0 + fcol + 4];
                unsigned ah[4], al[4];
                split_tf32(a0, ah[0], al[0]);
                split_tf32(a1, ah[1], al[1]);
                split_tf32(a2, ah[2], al[2]);
                split_tf32(a3, ah[3], al[3]);
                #pragma unroll
                for (int nt = 0; nt < 8; nt++) {
                    mma1688(d[mt][nt], ah, bh[nt]);   // hi*hi
                    mma1688(d[mt][nt], ah, bl[nt]);   // hi*lo
                    mma1688(d[mt][nt], al, bh[nt]);   // lo*hi
                }
            }
        }
    }

    // epilogue
    #pragma unroll
    for (int mt = 0; mt < 2; mt++) {
        const int row = m0 + wm*32 + mt*16 + frow;
        #pragma unroll
        for (int nt = 0; nt < 8; nt++) {
            const int col = n0 + wn*64 + nt*8 + fcol*2;
            float2 bv = make_float2(0.f, 0.f);
            if (bias) bv = *(const float2*)(bias + col);
            float2 o0 = make_float2(d[mt][nt][0] + bv.x, d[mt][nt][1] + bv.y);
            float2 o1 = make_float2(d[mt][nt][2] + bv.x, d[mt][nt][3] + bv.y);
            *(float2*)&C[(size_t)row * ldc + col]       = o0;
            *(float2*)&C[(size_t)(row + 8) * ldc + col] = o1;
        }
    }
}

// =================================================================
// Kernel 2: dots (one (h,p), 32-token tile vs 256 keys) + top-32
// (desc, ties -> smaller index), REDUX-based extraction.
// =================================================================
__global__ __launch_bounds__(256)
void dots_topk_kernel(const float* __restrict__ qm, const float* __restrict__ keys)
{
    __shared__ float As[8][36];     // [k][t]
    __shared__ float Bs[8][264];    // [k][n]
    __shared__ float dsm[32*256];   // [t][n]

    const int tid  = threadIdx.x;
    const int hp   = blockIdx.y;
    const int h    = hp >> 1;
    const int p    = hp & 1;
    const int t0g  = blockIdx.x * 32;

    const int ty   = tid >> 5;
    const int lane = tid & 31;

    const int at = tid >> 1;
    const int ak = (tid & 1) << 2;
    const float* Ap = qm + (size_t)(t0g + at) * 2048 + p*1024 + h*DH + ak;

    const int bn0 = tid >> 1;
    const int bn1 = bn0 + 128;
    const int bk  = (tid & 1) << 2;
    const float* Kb  = keys + (size_t)h * (NKEY*2*DH) + (size_t)p * DH;
    const float* Bp0 = Kb + (size_t)bn0 * (2*DH) + bk;
    const float* Bp1 = Kb + (size_t)bn1 * (2*DH) + bk;

    float4 ra = make_float4(0.f,0.f,0.f,0.f);
    if (tid < 64) ra = *(const float4*)Ap;
    float4 rb0 = *(const float4*)Bp0;
    float4 rb1 = *(const float4*)Bp1;

    float acc[4][8];
    #pragma unroll
    for (int r = 0; r < 4; r++)
        #pragma unroll
        for (int c = 0; c < 8; c++) acc[r][c] = 0.f;

    for (int s = 0; s < 16; s++) {
        __syncthreads();
        if (tid < 64) {
            As[ak+0][at] = ra.x; As[ak+1][at] = ra.y;
            As[ak+2][at] = ra.z; As[ak+3][at] = ra.w;
        }
        Bs[bk+0][bn0] = rb0.x; Bs[bk+1][bn0] = rb0.y;
        Bs[bk+2][bn0] = rb0.z; Bs[bk+3][bn0] = rb0.w;
        Bs[bk+0][bn1] = rb1.x; Bs[bk+1][bn1] = rb1.y;
        Bs[bk+2][bn1] = rb1.z; Bs[bk+3][bn1] = rb1.w;
        __syncthreads();
        if (s + 1 < 16) {
            if (tid < 64) ra = *(const float4*)(Ap + (s+1)*8);
            rb0 = *(const float4*)(Bp0 + (s+1)*8);
            rb1 = *(const float4*)(Bp1 + (s+1)*8);
        }
        #pragma unroll
        for (int kk = 0; kk < 8; kk++) {
            float4 a4 = *(const float4*)&As[kk][ty*4];
            float4 b0 = *(const float4*)&Bs[kk][lane*4];
            float4 b1 = *(const float4*)&Bs[kk][128 + lane*4];
            float ar[4] = {a4.x,a4.y,a4.z,a4.w};
            float bc[8] = {b0.x,b0.y,b0.z,b0.w,b1.x,b1.y,b1.z,b1.w};
            #pragma unroll
            for (int r = 0; r < 4; r++)
                #pragma unroll
                for (int c = 0; c < 8; c++)
                    acc[r][c] = fmaf(ar[r], bc[c], acc[r][c]);
        }
    }

    #pragma unroll
    for (int r = 0; r < 4; r++) {
        *(float4*)&dsm[(ty*4+r)*256 + lane*4]       = make_float4(acc[r][0],acc[r][1],acc[r][2],acc[r][3]);
        *(float4*)&dsm[(ty*4+r)*256 + 128 + lane*4] = make_float4(acc[r][4],acc[r][5],acc[r][6],acc[r][7]);
    }
    __syncthreads();

    #pragma unroll 1
    for (int it = 0; it < 4; it++) {
        const int t = ty*4 + it;
        float v[8];
        #pragma unroll
        for (int j = 0; j < 8; j++) v[j] = dsm[t*256 + j*32 + lane];
        unsigned taken = 0u;
        float outv = 0.f; int outn = 0;
        #pragma unroll 1
        for (int kk = 0; kk < 32; kk++) {
            float lv = neg_inf(); int ln = 0x7fffffff;
            #pragma unroll
            for (int j = 0; j < 8; j++) {
                float cand = ((taken >> j) & 1u) ? neg_inf() : v[j];
                if (cand > lv) { lv = cand; ln = j*32 + lane; }
            }
            const unsigned u    = ford(lv);
            const unsigned umax = __reduce_max_sync(0xffffffffu, u);
            const unsigned cln  = (u == umax) ? (unsigned)ln : 0xffffffffu;
            const unsigned wln  = __reduce_min_sync(0xffffffffu, cln);
            if (kk == lane) { outv = forddec(umax); outn = (int)wln; }
            if ((wln & 31u) == (unsigned)lane) taken |= 1u << (wln >> 5);
        }
        const size_t base = ((((size_t)(t0g + t)) * HEADS + h) * 2 + p) * TOPK;
        g_s1[base + lane] = outv;
        g_i1[base + lane] = outn;
    }
}

// =================================================================
// Kernel 3: combine (sorted-column pointer merge, REDUX argmax),
// softmax, 32-row value gather, weighted sum.
// =================================================================
__global__ __launch_bounds__(256)
void combine_kernel(const float* __restrict__ values)
{
    const int warp = threadIdx.x >> 5;
    const int lane = threadIdx.x & 31;
    const int slot = blockIdx.x * 8 + warp;
    const int t = slot & 2047;
    const int h = (slot >> 11) & 7;
    const int b = slot >> 14;
    const int u = t >> 1;
    const int p = t & 1;

    const size_t base0 = ((((size_t)(b*2048 + u))        * HEADS + h) * 2 + p) * TOPK;
    const size_t base1 = ((((size_t)(b*2048 + u + 1024)) * HEADS + h) * 2 + p) * TOPK;
    const float s0 = g_s1[base0 + lane];
    const int   i0 = g_i1[base0 + lane];
    const float s1 = g_s1[base1 + lane];
    const int   i1 = g_i1[base1 + lane];

    int ptr = 0;
    float rv = 0.f; int rflat = 0;
    #pragma unroll 1
    for (int it = 0; it < 32; it++) {
        const int pp = ptr < 32 ? ptr : 31;
        float cv = __shfl_sync(0xffffffffu, s0, pp) + s1;
        int fl = ptr * 32 + lane;
        if (ptr >= 32) { cv = neg_inf(); fl = 0x7fffffff; }
        const unsigned uu   = ford(cv);
        const unsigned umax = __reduce_max_sync(0xffffffffu, uu);
        const unsigned cfl  = (uu == umax) ? (unsigned)fl : 0xffffffffu;
        const unsigned wfl  = __reduce_min_sync(0xffffffffu, cfl);
        if (it == lane) { rv = forddec(umax); rflat = (int)wfl; }
        if ((wfl & 31u) == (unsigned)lane && wfl != 0xffffffffu) ptr++;
    }

    // softmax (lane 0 holds the max: extraction is in descending order)
    const float mx = __shfl_sync(0xffffffffu, rv, 0);
    float e = __expf(rv - mx);
    float ssum = e;
    #pragma unroll
    for (int o = 16; o > 0; o >>= 1) ssum += __shfl_xor_sync(0xffffffffu, ssum, o);
    const float w = e / ssum;

    const int si = rflat >> 5;
    const int sj = rflat & 31;
    const int iv0 = __shfl_sync(0xffffffffu, i0, si);
    const int iv1 = __shfl_sync(0xffffffffu, i1, sj);
    const int vi = iv0 * NKEY + iv1;

    const float* vb = values + (size_t)h * ((size_t)NKEY*NKEY) * DH;
    float4 acc = make_float4(0.f,0.f,0.f,0.f);
    #pragma unroll 4
    for (int k = 0; k < 32; k++) {
        const int   vik = __shfl_sync(0xffffffffu, vi, k);
        const float wk  = __shfl_sync(0xffffffffu, w,  k);
        const float4 row = *(const float4*)(vb + (size_t)vik * DH + lane*4);
        acc.x = fmaf(wk, row.x, acc.x);
        acc.y = fmaf(wk, row.y, acc.y);
        acc.z = fmaf(wk, row.z, acc.z);
        acc.w = fmaf(wk, row.w, acc.w);
    }
    *(float4*)&g_oh[(size_t)(b*2048 + t) * 1024 + h*DH + lane*4] = acc;
}

// =================================================================
extern "C" void kernel_launch(void* const* d_in, const int* in_sizes, int n_in,
                              void* d_out, int out_size)
{
    const float* x      = (const float*)d_in[0];
    const float* Wq     = (const float*)d_in[1];
    const float* keys   = (const float*)d_in[2];
    const float* values = (const float*)d_in[3];
    const float* Wo     = (const float*)d_in[4];
    const float* bo     = (const float*)d_in[5];
    float* out = (float*)d_out;

    float* q;  cudaGetSymbolAddress((void**)&q,  g_q);
    float* oh; cudaGetSymbolAddress((void**)&oh, g_oh);

    // 1) q = x @ Wq^T : [4096,1024] x [2048,1024]^T -> [4096,2048]
    mma_tn_x2<<<dim3(2048/128, 4096/128), 256>>>(x, Wq, q, nullptr,
                                                 4096, 2048, 1024, 1024, 1024, 2048);
    // 2) dots + stage-1 top-32
    dots_topk_kernel<<<dim3(4096/32, 16), 256>>>(q, keys);
    // 3) combine + softmax + gather
    combine_kernel<<<4096, 256>>>(values);
    // 4) out = oh @ Wo^T + bo : [4096,1024] x [1024,1024]^T -> [4096,1024]
    mma_tn_x2<<<dim3(1024/128, 4096/128), 256>>>(oh, Wo, out, bo,
                                                 4096, 1024, 1024, 1024, 1024, 1024);
}